// round 17
// baseline (speedup 1.0000x reference)
#include <cuda_runtime.h>

// out[b, f] = x0[b, f] * dot(x[b,:], w) + bias[f] + x[b, f]
// B = 16384 rows, F = 2048 cols, fp32. One CTA per row, 256 threads,
// each thread owns 8 columns (2 x float4).
//
// CONVERGED FINAL (held, unchanged). v4-family wall times over 6 runs:
// 61.47 / 61.47 / 61.50 / 61.50 / 61.50 / 61.50 us (0.05% spread).
// Identical-binary noise band: +/-0.35us. The kernel sits at the traffic
// floor: 402MB / ~6.5TB/s ~= 61.5us.
//
// Exhaustiveness: traffic is irreducible (3 fp32 streams touched exactly
// once; output dtype harness-fixed). Bandwidth is pinned at 6.3-6.55TB/s
// (DRAM 79-83%) across ELEVEN runs of SIX structurally distinct kernels:
// occ 50-97%, MLP 2-8, 256/512 thr, 1-2 rows/CTA, persistent vs
// multi-wave grids, 4 cache-policy combos, 128- vs 256-bit memory ops.
// That invariance == the HBM3e mixed 2:1 read/write turnaround ceiling.
//
// Design, each point measured against at least one alternative:
//  - 32 regs == EXACT occ-8 register-file cap (8 x 256 x 32 = 65536/SM);
//    any extra live register across the barrier measurably lost wall time.
//  - x / w loaded first (dot-critical path); x0 / bias in the epilogue.
//  - Single __syncthreads; 8 warp partials summed via broadcast LDS.
//  - 32-bit indexing (max byte offset 2^27): no 64-bit IMAD chains.
//  - Default cache policy: __ldcs regressed; __stcs / __stwt neutral.
//  - Rejected by measurement: persistent pipelined grid (+2.7us),
//    2 rows/CTA burst batching (+2.5us), 512-thr CTAs (+0.4us),
//    v8 256-bit ops (equal median, fewer low samples), full
//    front-batching (38 regs, occ 5-6: slower wall).

#define F_DIM 2048
#define VEC_PER_ROW (F_DIM / 4)   // 512 float4
#define THREADS 256
#define NWARPS (THREADS / 32)

__global__ __launch_bounds__(THREADS, 8)
void cross_fused_kernel(const float4* __restrict__ x0,
                        const float4* __restrict__ x,
                        const float4* __restrict__ w,
                        const float4* __restrict__ bias,
                        float4* __restrict__ out)
{
    const int tid  = threadIdx.x;
    const int base = blockIdx.x * VEC_PER_ROW;   // max 16384*512 = 2^23

    const int i0 = base + tid;
    const int i1 = i0 + THREADS;

    // Dot-critical loads first.
    float4 xa = x[i0];
    float4 xb = x[i1];
    float4 wa = w[tid];
    float4 wb = w[tid + THREADS];

    // Per-thread partial dot.
    float s = xa.x * wa.x + xa.y * wa.y + xa.z * wa.z + xa.w * wa.w
            + xb.x * wb.x + xb.y * wb.y + xb.z * wb.z + xb.w * wb.w;

    // Warp reduce.
    #pragma unroll
    for (int off = 16; off > 0; off >>= 1)
        s += __shfl_xor_sync(0xFFFFFFFFu, s, off);

    // Single-barrier cross-warp reduce: lane 0 publishes, everyone sums.
    __shared__ float warp_sums[NWARPS];
    const int lane = tid & 31;
    const int warp = tid >> 5;
    if (lane == 0) warp_sums[warp] = s;
    __syncthreads();

    float xw = 0.0f;
    #pragma unroll
    for (int i = 0; i < NWARPS; i++)
        xw += warp_sums[i];   // broadcast LDS, conflict-free

    // Epilogue loads (placed by ptxas within the 32-reg budget).
    float4 x0a = x0[i0];
    float4 x0b = x0[i1];
    float4 ba  = bias[tid];
    float4 bb  = bias[tid + THREADS];

    // out = x0 * xw + bias + x
    float4 oa, ob;
    oa.x = fmaf(x0a.x, xw, ba.x + xa.x);
    oa.y = fmaf(x0a.y, xw, ba.y + xa.y);
    oa.z = fmaf(x0a.z, xw, ba.z + xa.z);
    oa.w = fmaf(x0a.w, xw, ba.w + xa.w);
    ob.x = fmaf(x0b.x, xw, bb.x + xb.x);
    ob.y = fmaf(x0b.y, xw, bb.y + xb.y);
    ob.z = fmaf(x0b.z, xw, bb.z + xb.z);
    ob.w = fmaf(x0b.w, xw, bb.w + xb.w);

    out[i0] = oa;
    out[i1] = ob;
}

extern "C" void kernel_launch(void* const* d_in, const int* in_sizes, int n_in,
                              void* d_out, int out_size)
{
    const float4* x0   = (const float4*)d_in[0];
    const float4* x    = (const float4*)d_in[1];
    const float4* w    = (const float4*)d_in[2];
    const float4* bias = (const float4*)d_in[3];
    float4* out = (float4*)d_out;

    const int rows = in_sizes[0] / F_DIM;  // 16384
    cross_fused_kernel<<<rows, THREADS>>>(x0, x, w, bias, out);
}